// round 13
// baseline (speedup 1.0000x reference)
#include <cuda_runtime.h>
#include <cuda_bf16.h>
#include <cuda_fp16.h>
#include <math.h>
#include <stdint.h>

// Problem constants
#define B_  256
#define T_  128
#define DW_ 768
#define DH_ 768
#define G_  3072   // 4*DH
#define NBLK 96    // persistent LSTM blocks

// ---------------- scratch (device globals) -----------------------------------
__device__ uint32_t g_x16[(size_t)B_*T_*DW_/2];      // fp16x2 embeddings (t-major, sorted)
__device__ uint32_t g_wih16[384*G_];                 // W_ih top, k-pair packed fp16x2
__device__ uint32_t g_wh16[384*DH_];                 // Wh, k-pair packed fp16x2
__device__ float g_wpx[1536*DH_];                    // [Wp; Wx] stacked (1536 x 768)
__device__ float g_tx[B_*DW_];                       // target embeddings (sorted, fp32)
__device__ float g_txp[B_*G_];                       // tx @ W_ih_bot + b_lstm
__device__ uint32_t g_gin16[(size_t)B_*T_*G_/2];     // gate preacts fp16x2 (t-major)
__device__ __nv_bfloat16 g_hbuf[2][B_*DH_];          // bf16 h exchange (recurrence)
__device__ float g_H[(size_t)B_*T_*DH_];             // H fp32 (for rsum)
__device__ uint32_t g_H16[(size_t)B_*T_*DH_/2];      // H fp16x2 (for attention GEMM)
__device__ float g_scores[B_*T_];
__device__ float g_rh[B_*1536];                      // [r | h_last] concat (fp32)
__device__ float g_hstar[B_*DH_];
__device__ int   g_perm[B_];
__device__ int   g_lens_s[B_];
__device__ unsigned g_barcnt;

__device__ __forceinline__ float sigf(float x) { return 1.0f / (1.0f + expf(-x)); }

__device__ __forceinline__ uint32_t f2tf32(float f) {
    uint32_t u;
    asm("cvt.rna.tf32.f32 %0, %1;" : "=r"(u) : "f"(f));
    return u;
}
__device__ __forceinline__ uint32_t pack_bf16(float lo, float hi) {
    uint32_t r;
    asm("cvt.rn.bf16x2.f32 %0, %1, %2;" : "=r"(r) : "f"(hi), "f"(lo));
    return r;
}
__device__ __forceinline__ uint32_t pack_h2(float lo, float hi) {
    uint32_t r;
    asm("cvt.rn.f16x2.f32 %0, %1, %2;" : "=r"(r) : "f"(hi), "f"(lo));
    return r;
}

__device__ __forceinline__ void mma_tf32(float* c,
                                         uint32_t a0, uint32_t a1, uint32_t a2, uint32_t a3,
                                         uint32_t b0, uint32_t b1) {
    asm volatile(
        "mma.sync.aligned.m16n8k8.row.col.f32.tf32.tf32.f32 "
        "{%0,%1,%2,%3},{%4,%5,%6,%7},{%8,%9},{%0,%1,%2,%3};"
        : "+f"(c[0]), "+f"(c[1]), "+f"(c[2]), "+f"(c[3])
        : "r"(a0), "r"(a1), "r"(a2), "r"(a3), "r"(b0), "r"(b1));
}
__device__ __forceinline__ void mma_f16(float* c,
                                        uint32_t a0, uint32_t a1, uint32_t a2, uint32_t a3,
                                        uint32_t b0, uint32_t b1) {
    asm volatile(
        "mma.sync.aligned.m16n8k16.row.col.f32.f16.f16.f32 "
        "{%0,%1,%2,%3},{%4,%5,%6,%7},{%8,%9},{%0,%1,%2,%3};"
        : "+f"(c[0]), "+f"(c[1]), "+f"(c[2]), "+f"(c[3])
        : "r"(a0), "r"(a1), "r"(a2), "r"(a3), "r"(b0), "r"(b1));
}
__device__ __forceinline__ void mma_bf16(float* c,
                                         uint32_t a0, uint32_t a1, uint32_t a2, uint32_t a3,
                                         uint32_t b0, uint32_t b1) {
    asm volatile(
        "mma.sync.aligned.m16n8k16.row.col.f32.bf16.bf16.f32 "
        "{%0,%1,%2,%3},{%4,%5,%6,%7},{%8,%9},{%0,%1,%2,%3};"
        : "+f"(c[0]), "+f"(c[1]), "+f"(c[2]), "+f"(c[3])
        : "r"(a0), "r"(a1), "r"(a2), "r"(a3), "r"(b0), "r"(b1));
}
__device__ __forceinline__ void ldsm4(uint32_t& r0, uint32_t& r1,
                                      uint32_t& r2, uint32_t& r3, uint32_t addr) {
    asm volatile("ldmatrix.sync.aligned.m8n8.x4.shared.b16 {%0,%1,%2,%3}, [%4];"
                 : "=r"(r0), "=r"(r1), "=r"(r2), "=r"(r3) : "r"(addr));
}

__device__ __forceinline__ void cpa16(uint32_t dst, const void* src) {
    asm volatile("cp.async.ca.shared.global [%0], [%1], 16;"
                 :: "r"(dst), "l"(src));
}
__device__ __forceinline__ void cpa_commit() {
    asm volatile("cp.async.commit_group;" ::: "memory");
}
template<int N>
__device__ __forceinline__ void cpa_wait() {
    asm volatile("cp.async.wait_group %0;" :: "n"(N) : "memory");
}

// ---------------- sort batch by length (descending), one block ---------------
__global__ void sort_kernel(const int* __restrict__ lens) {
    __shared__ int key[B_];
    int tid = threadIdx.x;
    key[tid] = ((128 - lens[tid]) << 8) | tid;
    __syncthreads();
    for (int k = 2; k <= B_; k <<= 1) {
        for (int j = k >> 1; j > 0; j >>= 1) {
            int ixj = tid ^ j;
            if (ixj > tid) {
                int a = key[tid], b = key[ixj];
                bool up = ((tid & k) == 0);
                if (up ? (a > b) : (a < b)) { key[tid] = b; key[ixj] = a; }
            }
            __syncthreads();
        }
    }
    g_perm[tid] = key[tid] & 255;
    g_lens_s[tid] = 128 - (key[tid] >> 8);
}

// ---------------- gather+convert x -> fp16 (t-major); gather tx fp32 ---------
__global__ void gatherx_kernel(const int* __restrict__ sent,
                               const int* __restrict__ target,
                               const float* __restrict__ emb,
                               const float* __restrict__ temb) {
    int row = blockIdx.x;
    int tid = threadIdx.x;  // 192
    if (row < B_ * T_) {
        int bs = row & 255, t = row >> 8;
        int token = sent[g_perm[bs] * T_ + t];
        const float2* src = (const float2*)(emb + (size_t)token * DW_);
        uint32_t* dst = g_x16 + (size_t)row * (DW_ / 2);
        float2 v0 = src[tid];
        float2 v1 = src[tid + 192];
        dst[tid] = pack_h2(v0.x, v0.y);
        dst[tid + 192] = pack_h2(v1.x, v1.y);
    } else {
        int bs = row - B_ * T_;
        const float4* src = (const float4*)(temb + (size_t)target[g_perm[bs]] * DW_);
        ((float4*)(g_tx + (size_t)bs * DW_))[tid] = src[tid];
    }
}

// ---------------- pack weights: W_ih top + Wh fp16 pairs, stack [Wp;Wx] ------
__global__ void convw_kernel(const float* __restrict__ W_ih,
                             const float* __restrict__ Wh,
                             const float* __restrict__ Wp,
                             const float* __restrict__ Wx) {
    int i = blockIdx.x * 256 + threadIdx.x;
    if (i < 384 * G_) {
        int k2 = i / G_, n = i - k2 * G_;
        g_wih16[i] = pack_h2(W_ih[(size_t)(2 * k2) * G_ + n],
                             W_ih[(size_t)(2 * k2 + 1) * G_ + n]);
    } else if (i < 384 * G_ + 384 * DH_) {
        int j = i - 384 * G_;
        int k2 = j / DH_, n = j - k2 * DH_;
        g_wh16[j] = pack_h2(Wh[(size_t)(2 * k2) * DH_ + n],
                            Wh[(size_t)(2 * k2 + 1) * DH_ + n]);
    } else {
        int j = i - 384 * G_ - 384 * DH_;
        if (j < 1536 * DH_)
            g_wpx[j] = (j < 768 * DH_) ? Wp[j] : Wx[j - 768 * DH_];
    }
}

// zero bf16 h (buffer 0), scores, barrier counter
__global__ void zeroall_kernel() {
    int i = blockIdx.x * 256 + threadIdx.x;
    if (i < B_ * DH_ / 2) ((uint32_t*)g_hbuf)[i] = 0u;
    if (i < B_ * T_) g_scores[i] = 0.0f;
    if (i == 0) g_barcnt = 0u;
}

// ---------------- fp16 cp.async pipelined 128x128 GEMM (ldmatrix A) ----------
// MODE 2: gin: C16 = fp16(acc + aux[(row&255)*auxStride + col])
// MODE 4: attn: atomicAdd(sc[(row&255)*T + (row>>8)], sum_col tanh(acc)*wv[col])
template<int MODE>
__global__ void __launch_bounds__(256, 2)
mm2h(const uint32_t* __restrict__ Au, const uint32_t* __restrict__ Bp,
     uint32_t* __restrict__ C16, int N,
     const float* __restrict__ aux, long long auxStride,
     const float* __restrict__ wv, float* __restrict__ sc,
     const int* __restrict__ exl) {
    constexpr int BM = 128, BN = 128, S = 3;
    constexpr int SA = 20;
    constexpr int SB = 136;
    constexpr int ASTG = BM * SA;
    constexpr int BSTG = 16 * SB;
    constexpr int KT = 768 / 32;      // 24

    const int m0 = blockIdx.y * BM;
    {
        int t = m0 >> 8;
        int half = (m0 >> 7) & 1;
        if (t >= exl[half * 128]) return;
    }

    extern __shared__ uint32_t smu[];
    uint32_t* As = smu;
    uint32_t* Bs = smu + S * ASTG;

    const int tid = threadIdx.x;
    const int lane = tid & 31;
    const int wid = tid >> 5;
    const int wm = wid & 1;
    const int wn = wid >> 1;
    const int n0 = blockIdx.x * BN;

    const int arow = tid >> 1;
    const int abase = (tid & 1) * 8;
    const uint32_t* aptr = Au + (size_t)(m0 + arow) * 384 + abase;
    const int brow = tid >> 4;
    const int bbase = (tid & 15) * 8;
    const uint32_t* bptr = Bp + (size_t)brow * N + n0 + bbase;

    const uint32_t As_sh = (uint32_t)__cvta_generic_to_shared(As);
    uint32_t rowoffA[4];
#pragma unroll
    for (int mt = 0; mt < 4; mt++)
        rowoffA[mt] = ((wm * 64 + mt * 16 + (lane & 15)) * SA + (lane >> 4) * 4) * 4;

    float acc[4][4][4];
#pragma unroll
    for (int i = 0; i < 4; i++)
#pragma unroll
        for (int j = 0; j < 4; j++)
#pragma unroll
            for (int q = 0; q < 4; q++) acc[i][j][q] = 0.0f;

    auto issue = [&](int kt) {
        int st = kt % S;
        uint32_t* as = As + st * ASTG;
        uint32_t* bs = Bs + st * BSTG;
        const uint32_t* ap = aptr + kt * 16;
        const uint32_t* bp = bptr + (size_t)kt * 16 * N;
        cpa16((uint32_t)__cvta_generic_to_shared(as + arow * SA + abase), ap);
        cpa16((uint32_t)__cvta_generic_to_shared(as + arow * SA + abase + 4), ap + 4);
        cpa16((uint32_t)__cvta_generic_to_shared(bs + brow * SB + bbase), bp);
        cpa16((uint32_t)__cvta_generic_to_shared(bs + brow * SB + bbase + 4), bp + 4);
    };

#pragma unroll
    for (int s = 0; s < S - 1; s++) { issue(s); cpa_commit(); }

    for (int kt = 0; kt < KT; kt++) {
        cpa_wait<S - 2>();
        __syncthreads();
        if (kt + S - 1 < KT) issue(kt + S - 1);
        cpa_commit();

        const int st = kt % S;
        const uint32_t abyte = As_sh + (st * ASTG) * 4;
        const uint32_t* bsU = Bs + st * BSTG;
#pragma unroll
        for (int ks = 0; ks < 2; ks++) {
            int kq = ks * 8 + (lane & 3);
            uint32_t af[4][4], bf[4][2];
#pragma unroll
            for (int mt = 0; mt < 4; mt++)
                ldsm4(af[mt][0], af[mt][1], af[mt][2], af[mt][3],
                      abyte + rowoffA[mt] + ks * 32);
#pragma unroll
            for (int nt = 0; nt < 4; nt++) {
                int n = wn * 32 + nt * 8 + (lane >> 2);
                bf[nt][0] = bsU[kq * SB + n];
                bf[nt][1] = bsU[(kq + 4) * SB + n];
            }
#pragma unroll
            for (int mt = 0; mt < 4; mt++)
#pragma unroll
                for (int nt = 0; nt < 4; nt++)
                    mma_f16(acc[mt][nt],
                            af[mt][0], af[mt][1], af[mt][2], af[mt][3],
                            bf[nt][0], bf[nt][1]);
        }
    }

    if (MODE == 4) {
#pragma unroll
        for (int mt = 0; mt < 4; mt++) {
            float pl = 0.0f, ph = 0.0f;
#pragma unroll
            for (int nt = 0; nt < 4; nt++) {
                int col = n0 + wn * 32 + nt * 8 + ((lane & 3) << 1);
                float w0 = wv[col], w1 = wv[col + 1];
                pl += tanhf(acc[mt][nt][0]) * w0 + tanhf(acc[mt][nt][1]) * w1;
                ph += tanhf(acc[mt][nt][2]) * w0 + tanhf(acc[mt][nt][3]) * w1;
            }
            pl += __shfl_xor_sync(0xffffffffu, pl, 1);
            pl += __shfl_xor_sync(0xffffffffu, pl, 2);
            ph += __shfl_xor_sync(0xffffffffu, ph, 1);
            ph += __shfl_xor_sync(0xffffffffu, ph, 2);
            if ((lane & 3) == 0) {
                int r = m0 + wm * 64 + mt * 16 + (lane >> 2);
                atomicAdd(&sc[(r & 255) * T_ + (r >> 8)], pl);
                atomicAdd(&sc[((r + 8) & 255) * T_ + ((r + 8) >> 8)], ph);
            }
        }
    } else {
        const int N2 = N >> 1;
#pragma unroll
        for (int mt = 0; mt < 4; mt++) {
#pragma unroll
            for (int nt = 0; nt < 4; nt++) {
                int r = m0 + wm * 64 + mt * 16 + (lane >> 2);
                int c = n0 + wn * 32 + nt * 8 + ((lane & 3) << 1);
                float v0 = acc[mt][nt][0], v1 = acc[mt][nt][1];
                float v2 = acc[mt][nt][2], v3 = acc[mt][nt][3];
                const float* ar  = aux + (size_t)(r & 255) * auxStride;
                const float* ar8 = aux + (size_t)((r + 8) & 255) * auxStride;
                v0 += ar[c];  v1 += ar[c + 1];
                v2 += ar8[c]; v3 += ar8[c + 1];
                C16[(size_t)r * N2 + (c >> 1)] = pack_h2(v0, v1);
                C16[(size_t)(r + 8) * N2 + (c >> 1)] = pack_h2(v2, v3);
            }
        }
    }
}

// ---------------- small tf32 GEMM (64x64 tiles) -------------------------------
// MODE 1: C = acc + aux[col];  MODE 6: C = tanh(acc)
template<int BM, int BN, int WM, int WN, int MODE>
__global__ void __launch_bounds__((BM/WM)*(BN/WN)*32)
mm_k(const float* __restrict__ A, const float* __restrict__ Bm,
     float* __restrict__ C, int M, int N, int K,
     const float* __restrict__ aux) {
    constexpr int BK = 16;
    constexpr int NWARP = (BM / WM) * (BN / WN);
    constexpr int NT = NWARP * 32;
    constexpr int SA = BK + 4;
    constexpr int SB = BN + 8;
    constexpr int MT = WM / 16;
    constexpr int NL = WN / 8;
    constexpr int AQ = (BM * 4) / NT;
    constexpr int BQ = (BN * 4) / NT;

    __shared__ __align__(16) uint32_t As[BM][SA];
    __shared__ __align__(16) uint32_t Bs[BK][SB];

    const int tid = threadIdx.x;
    const int lane = tid & 31;
    const int wid = tid >> 5;
    const int wm = wid % (BM / WM);
    const int wn = wid / (BM / WM);
    const int m0 = blockIdx.y * BM;
    const int n0 = blockIdx.x * BN;

    float acc[MT][NL][4];
#pragma unroll
    for (int i = 0; i < MT; i++)
#pragma unroll
        for (int j = 0; j < NL; j++)
#pragma unroll
            for (int q = 0; q < 4; q++) acc[i][j][q] = 0.0f;

    float4 pa[AQ], pb[BQ];
    const int KT = K / BK;

#pragma unroll
    for (int q = 0; q < AQ; q++) {
        int idx = tid + q * NT;
        pa[q] = *(const float4*)(A + (size_t)(m0 + (idx >> 2)) * K + ((idx & 3) << 2));
    }
#pragma unroll
    for (int q = 0; q < BQ; q++) {
        int idx = tid + q * NT;
        pb[q] = *(const float4*)(Bm + (size_t)(idx / (BN / 4)) * N + n0 + ((idx % (BN / 4)) << 2));
    }

    for (int kt = 0; kt < KT; kt++) {
#pragma unroll
        for (int q = 0; q < AQ; q++) {
            int idx = tid + q * NT;
            uint4 v = make_uint4(f2tf32(pa[q].x), f2tf32(pa[q].y),
                                 f2tf32(pa[q].z), f2tf32(pa[q].w));
            *(uint4*)&As[idx >> 2][(idx & 3) << 2] = v;
        }
#pragma unroll
        for (int q = 0; q < BQ; q++) {
            int idx = tid + q * NT;
            uint4 v = make_uint4(f2tf32(pb[q].x), f2tf32(pb[q].y),
                                 f2tf32(pb[q].z), f2tf32(pb[q].w));
            *(uint4*)&Bs[idx / (BN / 4)][(idx % (BN / 4)) << 2] = v;
        }
        __syncthreads();

        if (kt + 1 < KT) {
            int k0 = (kt + 1) * BK;
#pragma unroll
            for (int q = 0; q < AQ; q++) {
                int idx = tid + q * NT;
                pa[q] = *(const float4*)(A + (size_t)(m0 + (idx >> 2)) * K + k0 + ((idx & 3) << 2));
            }
#pragma unroll
            for (int q = 0; q < BQ; q++) {
                int idx = tid + q * NT;
                pb[q] = *(const float4*)(Bm + (size_t)(k0 + idx / (BN / 4)) * N + n0 + ((idx % (BN / 4)) << 2));
            }
        }

#pragma unroll
        for (int ks = 0; ks < 2; ks++) {
            uint32_t af[MT][4];
            uint32_t bf[NL][2];
            int kc = ks * 8 + (lane & 3);
#pragma unroll
            for (int mt = 0; mt < MT; mt++) {
                int r = wm * WM + mt * 16 + (lane >> 2);
                af[mt][0] = As[r][kc];
                af[mt][1] = As[r + 8][kc];
                af[mt][2] = As[r][kc + 4];
                af[mt][3] = As[r + 8][kc + 4];
            }
#pragma unroll
            for (int nt = 0; nt < NL; nt++) {
                int n = wn * WN + nt * 8 + (lane >> 2);
                bf[nt][0] = Bs[kc][n];
                bf[nt][1] = Bs[kc + 4][n];
            }
#pragma unroll
            for (int mt = 0; mt < MT; mt++)
#pragma unroll
                for (int nt = 0; nt < NL; nt++)
                    mma_tf32(acc[mt][nt],
                             af[mt][0], af[mt][1], af[mt][2], af[mt][3],
                             bf[nt][0], bf[nt][1]);
        }
        __syncthreads();
    }

#pragma unroll
    for (int mt = 0; mt < MT; mt++) {
#pragma unroll
        for (int nt = 0; nt < NL; nt++) {
            int r = m0 + wm * WM + mt * 16 + (lane >> 2);
            int c = n0 + wn * WN + nt * 8 + ((lane & 3) << 1);
            float v0 = acc[mt][nt][0], v1 = acc[mt][nt][1];
            float v2 = acc[mt][nt][2], v3 = acc[mt][nt][3];
            if (MODE == 1) {
                v0 += aux[c]; v1 += aux[c + 1];
                v2 += aux[c]; v3 += aux[c + 1];
            }
            if (MODE == 6) {
                v0 = tanhf(v0); v1 = tanhf(v1);
                v2 = tanhf(v2); v3 = tanhf(v3);
            }
            *(float2*)&C[(size_t)r * N + c] = make_float2(v0, v1);
            *(float2*)&C[(size_t)(r + 8) * N + c] = make_float2(v2, v3);
        }
    }
}

// ---------------- persistent fused LSTM recurrence (bf16 MMA, cp.async) ------
// Identical structure to the R8/R10 proven version; h_last -> g_rh[:,768:].
__global__ void __launch_bounds__(256, 1)
lstm_persist(const float* __restrict__ W_hh) {
    extern __shared__ uint32_t sm_[];
    uint32_t* ws = sm_;                        // 12288
    uint32_t* Ab = sm_ + 12288;                // 34816
    int* slens = (int*)(sm_ + 12288 + 34816);
    int* nact  = (int*)(sm_ + 12288 + 34816 + 256);

    const int tid = threadIdx.x;
    const int lane = tid & 31;
    const int w = tid >> 5;
    const int nb = blockIdx.x;

    for (int i = tid; i < 12288; i += 256) {
        int nt = i / 3072;
        int rem = i - nt * 3072;
        int k2 = rem >> 3, nn = rem & 7;
        int col = nt * 768 + nb * 8 + nn;
        float w0 = W_hh[(size_t)(2 * k2) * G_ + col];
        float w1 = W_hh[(size_t)(2 * k2 + 1) * G_ + col];
        ws[i] = pack_bf16(w0, w1);
    }
    slens[tid] = g_lens_s[tid];
    __syncthreads();
    for (int i = tid; i < T_; i += 256) {
        int c = 0;
        for (int b = 0; b < B_; b++) c += (slens[b] > i) ? 1 : 0;
        int n32 = (c + 31) & ~31;
        nact[i] = n32 > 256 ? 256 : n32;
    }
    __syncthreads();

    const uint32_t Ab_sh = (uint32_t)__cvta_generic_to_shared(Ab);
    uint32_t rowoffA[2];
#pragma unroll
    for (int mt = 0; mt < 2; mt++)
        rowoffA[mt] = ((w * 32 + mt * 16 + (lane & 15)) * 68 + (lane >> 4) * 4) * 4;

    float c_reg[2][4], h_reg[2][4];
#pragma unroll
    for (int i = 0; i < 2; i++)
#pragma unroll
        for (int q = 0; q < 4; q++) { c_reg[i][q] = 0.0f; h_reg[i][q] = 0.0f; }

    unsigned epoch = 0;

    for (int t = 0; t < T_; t++) {
        const uint32_t* hcur = (const uint32_t*)g_hbuf[t & 1];
        __nv_bfloat16* hnxt = g_hbuf[(t + 1) & 1];
        const int n32 = nact[t];
        const bool sact = (tid < n32);
        const bool wact = (w * 32 < n32);

        float acc[2][4][4];
#pragma unroll
        for (int i = 0; i < 2; i++)
#pragma unroll
            for (int j = 0; j < 4; j++)
#pragma unroll
                for (int q = 0; q < 4; q++) acc[i][j][q] = 0.0f;

        const uint32_t* hrow = hcur + (size_t)tid * 384;
        const uint32_t dstrow = Ab_sh + tid * 68 * 4;

        if (sact) {
#pragma unroll
            for (int j = 0; j < 16; j++)
                cpa16(dstrow + j * 16, hrow + j * 4);
        }
        cpa_commit();

        for (int cch = 0; cch < 6; cch++) {
            cpa_wait<0>();
            __syncthreads();
            if (cch < 5) {
                if (sact) {
                    uint32_t d = dstrow + (((cch + 1) & 1) ? 17408u * 4u : 0u);
                    const uint32_t* s = hrow + (cch + 1) * 64;
#pragma unroll
                    for (int j = 0; j < 16; j++)
                        cpa16(d + j * 16, s + j * 4);
                }
                cpa_commit();
            }
            if (wact) {
                const uint32_t abyte = Ab_sh + (cch & 1) * 17408 * 4;
#pragma unroll
                for (int s = 0; s < 8; s++) {
                    int k2 = cch * 64 + s * 8 + (lane & 3);
                    uint32_t af[2][4], bf[4][2];
#pragma unroll
                    for (int mt = 0; mt < 2; mt++)
                        ldsm4(af[mt][0], af[mt][1], af[mt][2], af[mt][3],
                              abyte + rowoffA[mt] + s * 32);
#pragma unroll
                    for (int nt = 0; nt < 4; nt++) {
                        bf[nt][0] = ws[nt * 3072 + k2 * 8 + (lane >> 2)];
                        bf[nt][1] = ws[nt * 3072 + (k2 + 4) * 8 + (lane >> 2)];
                    }
#pragma unroll
                    for (int mt = 0; mt < 2; mt++)
#pragma unroll
                        for (int nt = 0; nt < 4; nt++)
                            mma_bf16(acc[mt][nt],
                                     af[mt][0], af[mt][1], af[mt][2], af[mt][3],
                                     bf[nt][0], bf[nt][1]);
                }
            }
        }

        int jcol = nb * 8 + ((lane & 3) << 1);
#pragma unroll
        for (int mt = 0; mt < 2; mt++) {
#pragma unroll
            for (int half = 0; half < 2; half++) {
                int r = w * 32 + mt * 16 + (lane >> 2) + half * 8;
                bool valid = (t < slens[r]);
                float2 bi = make_float2(0.f, 0.f), bff = bi, bg = bi, bo = bi;
                if (valid) {
                    const uint32_t* gp = g_gin16 + ((size_t)(t * B_ + r)) * (G_ / 2) + (jcol >> 1);
                    bi  = __half22float2(*(const __half2*)&gp[0]);
                    bff = __half22float2(*(const __half2*)&gp[384]);
                    bg  = __half22float2(*(const __half2*)&gp[768]);
                    bo  = __half22float2(*(const __half2*)&gp[1152]);
                }
                float hv0, hv1;
#pragma unroll
                for (int sub = 0; sub < 2; sub++) {
                    int q = half * 2 + sub;
                    float iv = acc[mt][0][q] + (sub ? bi.y : bi.x);
                    float fv = acc[mt][1][q] + (sub ? bff.y : bff.x);
                    float gv = acc[mt][2][q] + (sub ? bg.y : bg.x);
                    float ov = acc[mt][3][q] + (sub ? bo.y : bo.x);
                    float cn = sigf(fv) * c_reg[mt][q] + sigf(iv) * tanhf(gv);
                    float hn = sigf(ov) * tanhf(cn);
                    c_reg[mt][q] = valid ? cn : c_reg[mt][q];
                    float hv = valid ? hn : h_reg[mt][q];
                    h_reg[mt][q] = hv;
                    if (sub == 0) hv0 = hv; else hv1 = hv;
                }
                *(uint32_t*)&hnxt[(size_t)r * DH_ + jcol] = pack_bf16(hv0, hv1);
                *(float2*)&g_H[((size_t)(t * B_ + r)) * DH_ + jcol] = make_float2(hv0, hv1);
                g_H16[((size_t)(t * B_ + r)) * (DH_ / 2) + (jcol >> 1)] = pack_h2(hv0, hv1);
                if (t == T_ - 1)
                    *(float2*)&g_rh[(size_t)r * 1536 + 768 + jcol] = make_float2(hv0, hv1);
            }
        }

        // ---- grid barrier ----
        __syncthreads();
        if (tid == 0) {
            asm volatile("red.release.gpu.global.add.u32 [%0], %1;"
                         :: "l"(&g_barcnt), "r"(1u) : "memory");
            epoch++;
            unsigned target = epoch * NBLK;
            unsigned v;
            do {
                asm volatile("ld.acquire.gpu.global.u32 %0, [%1];"
                             : "=r"(v) : "l"(&g_barcnt));
                if (v < target) __nanosleep(64);
            } while (v < target);
        }
        __syncthreads();
    }
}

// ---------------- fused masked softmax + r = alpha.H -> g_rh[:, :768] --------
__global__ void softrsum_kernel() {
    int b = blockIdx.x;
    int tid = threadIdx.x;  // 256
    int lane = tid & 31, wid = tid >> 5;
    __shared__ float al[T_];
    __shared__ float red[8], red2[8];
    __shared__ int slen;
    if (tid == 0) slen = g_lens_s[b];
    __syncthreads();
    int len = slen;
    float s = (tid < len) ? g_scores[b * T_ + tid] : -1e30f;

    float m = s;
#pragma unroll
    for (int off = 16; off > 0; off >>= 1)
        m = fmaxf(m, __shfl_down_sync(0xffffffffu, m, off));
    if (lane == 0) red[wid] = m;
    __syncthreads();
    if (tid == 0) {
        float mm = red[0];
#pragma unroll
        for (int i = 1; i < 8; i++) mm = fmaxf(mm, red[i]);
        red[0] = mm;
    }
    __syncthreads();
    float mx = red[0];

    float e = (tid < len) ? expf(s - mx) : 0.0f;
    float sum = e;
#pragma unroll
    for (int off = 16; off > 0; off >>= 1)
        sum += __shfl_down_sync(0xffffffffu, sum, off);
    if (lane == 0) red2[wid] = sum;
    __syncthreads();
    if (tid == 0) {
        float tt = 0.0f;
#pragma unroll
        for (int i = 0; i < 8; i++) tt += red2[i];
        red2[0] = tt;
    }
    __syncthreads();
    float tot = red2[0];
    if (tid < T_) al[tid] = e / tot;
    __syncthreads();

    float a0 = 0.0f, a1 = 0.0f, a2 = 0.0f;
#pragma unroll 4
    for (int t = 0; t < len; t++) {
        float a = al[t];
        const float* Hr = g_H + ((size_t)(t * B_ + b)) * DH_;
        a0 += a * Hr[tid];
        a1 += a * Hr[tid + 256];
        a2 += a * Hr[tid + 512];
    }
    g_rh[b * 1536 + tid] = a0;
    g_rh[b * 1536 + tid + 256] = a1;
    g_rh[b * 1536 + tid + 512] = a2;
}

// ---------------- logit = h_star @ W_lin + b_lin (unsort at write) -----------
__global__ void logit_kernel(const float* __restrict__ Wl,
                             const float* __restrict__ bl,
                             float* __restrict__ out) {
    int b = blockIdx.x;
    int tid = threadIdx.x;
    float p0 = 0.0f, p1 = 0.0f, p2 = 0.0f;
    for (int j = tid; j < DH_; j += 128) {
        float v = g_hstar[b * DH_ + j];
        p0 += v * Wl[j * 3 + 0];
        p1 += v * Wl[j * 3 + 1];
        p2 += v * Wl[j * 3 + 2];
    }
#pragma unroll
    for (int off = 16; off > 0; off >>= 1) {
        p0 += __shfl_down_sync(0xffffffffu, p0, off);
        p1 += __shfl_down_sync(0xffffffffu, p1, off);
        p2 += __shfl_down_sync(0xffffffffu, p2, off);
    }
    __shared__ float sm[3][4];
    if ((tid & 31) == 0) {
        sm[0][tid >> 5] = p0; sm[1][tid >> 5] = p1; sm[2][tid >> 5] = p2;
    }
    __syncthreads();
    if (tid < 3) {
        float s = sm[tid][0] + sm[tid][1] + sm[tid][2] + sm[tid][3];
        out[g_perm[b] * 3 + tid] = s + bl[tid];
    }
}

// ---------------- launch ------------------------------------------------------
extern "C" void kernel_launch(void* const* d_in, const int* in_sizes, int n_in,
                              void* d_out, int out_size) {
    const int*   sent   = (const int*)d_in[0];
    const int*   target = (const int*)d_in[1];
    const int*   lens   = (const int*)d_in[2];
    const float* emb    = (const float*)d_in[3];
    const float* temb   = (const float*)d_in[4];
    const float* W_ih   = (const float*)d_in[5];   // (1536, 3072)
    const float* W_hh   = (const float*)d_in[6];   // (768, 3072)
    const float* b_lstm = (const float*)d_in[7];   // (3072,)
    const float* Wh     = (const float*)d_in[8];   // (768, 768)
    // d_in[9] = Wv — unused: aspect score term constant over t, cancels in softmax.
    const float* w_att  = (const float*)d_in[10];  // (1536,), first 768 used
    const float* Wp     = (const float*)d_in[11];
    const float* Wx     = (const float*)d_in[12];
    const float* W_lin  = (const float*)d_in[13];  // (768, 3)
    const float* b_lin  = (const float*)d_in[14];
    float* out = (float*)d_out;

    float *ptx, *ptxp, *prh, *pwpx, *phstar, *pscores;
    uint32_t *px16, *pwih16, *pwh16, *pgin16, *pH16;
    int *plens_s;
    cudaGetSymbolAddress((void**)&ptx,     g_tx);
    cudaGetSymbolAddress((void**)&ptxp,    g_txp);
    cudaGetSymbolAddress((void**)&prh,     g_rh);
    cudaGetSymbolAddress((void**)&pwpx,    g_wpx);
    cudaGetSymbolAddress((void**)&phstar,  g_hstar);
    cudaGetSymbolAddress((void**)&pscores, g_scores);
    cudaGetSymbolAddress((void**)&plens_s, g_lens_s);
    cudaGetSymbolAddress((void**)&px16,    g_x16);
    cudaGetSymbolAddress((void**)&pwih16,  g_wih16);
    cudaGetSymbolAddress((void**)&pwh16,   g_wh16);
    cudaGetSymbolAddress((void**)&pgin16,  g_gin16);
    cudaGetSymbolAddress((void**)&pH16,    g_H16);

    const int LSTM_SMEM = (12288 + 34816) * 4 + 256 * 4 + 128 * 4;  // 189,952 B
    cudaFuncSetAttribute(lstm_persist,
                         cudaFuncAttributeMaxDynamicSharedMemorySize, LSTM_SMEM);
    const int MM2H_SMEM = 3 * (2560 + 2176) * 4;  // 56,832 B (2 CTAs/SM)
    cudaFuncSetAttribute(mm2h<2>,
                         cudaFuncAttributeMaxDynamicSharedMemorySize, MM2H_SMEM);
    cudaFuncSetAttribute(mm2h<4>,
                         cudaFuncAttributeMaxDynamicSharedMemorySize, MM2H_SMEM);

    // 1. sort batch by length (descending)
    sort_kernel<<<1, B_>>>(lens);

    // 2. gather+convert x -> fp16 (t-major), gather tx (fp32)
    gatherx_kernel<<<B_ * T_ + B_, 192>>>(sent, target, emb, temb);

    // 3. pack W_ih_top / Wh fp16 pairs + stack [Wp;Wx]
    convw_kernel<<<(384 * G_ + 384 * DH_ + 1536 * DH_ + 255) / 256, 256>>>(
        W_ih, Wh, Wp, Wx);

    // 4. zero h buffer (bf16), scores, barrier counter
    zeroall_kernel<<<(B_ * DH_ / 2 + 255) / 256, 256>>>();

    // 5. txp = tx @ W_ih[768:,:] + b_lstm      (256 x 3072, K=768, tf32)
    mm_k<64, 64, 32, 32, 1><<<dim3(G_ / 64, B_ / 64), 128>>>(
        ptx, W_ih + (size_t)768 * G_, ptxp, B_, G_, DW_, b_lstm);

    // 6. gin = x16 @ Wih16 + txp[bs]   (fp16 MMA, ldmatrix, early-exit)
    mm2h<2><<<dim3(G_ / 128, (B_ * T_) / 128), 256, MM2H_SMEM>>>(
        px16, pwih16, pgin16, G_,
        ptxp, G_, nullptr, nullptr, plens_s);

    // 7. fused persistent LSTM recurrence
    lstm_persist<<<NBLK, 256, LSTM_SMEM>>>(W_hh);

    // 8. attention scores (fp16 MMA, ldmatrix, early-exit)
    mm2h<4><<<dim3(DH_ / 128, (B_ * T_) / 128), 256, MM2H_SMEM>>>(
        pH16, pwh16, nullptr, DH_,
        nullptr, 0, w_att, pscores, plens_s);

    // 9. fused masked softmax + r-sum -> g_rh[:, :768]
    softrsum_kernel<<<B_, 256>>>();

    // 10. h_star = tanh([r | h_last] @ [Wp; Wx])   (K=1536, tanh epilogue)
    mm_k<64, 64, 32, 32, 6><<<dim3(DH_ / 64, B_ / 64), 128>>>(
        prh, pwpx, phstar, B_, DH_, 1536, nullptr);

    // 11. logits (unsorted write)
    logit_kernel<<<B_, 128>>>(W_lin, b_lin, out);
}

// round 14
// speedup vs baseline: 1.4824x; 1.4824x over previous
#include <cuda_runtime.h>
#include <cuda_bf16.h>
#include <cuda_fp16.h>
#include <math.h>
#include <stdint.h>

// Problem constants
#define B_  256
#define T_  128
#define DW_ 768
#define DH_ 768
#define G_  3072   // 4*DH
#define NBLK 96    // persistent LSTM blocks

// ---------------- scratch (device globals) -----------------------------------
__device__ uint32_t g_x16[(size_t)B_*T_*DW_/2];      // fp16x2 embeddings (t-major, sorted)
__device__ uint32_t g_wih16[384*G_];                 // W_ih top, k-pair packed fp16x2
__device__ uint32_t g_wh16[384*DH_];                 // Wh, k-pair packed fp16x2
__device__ float g_wpx[1536*DH_];                    // [Wp; Wx] stacked (1536 x 768)
__device__ float g_tx[B_*DW_];                       // target embeddings (sorted, fp32)
__device__ float g_txp[B_*G_];                       // tx @ W_ih_bot + b_lstm
__device__ uint32_t g_gin16[(size_t)B_*T_*G_/2];     // gate preacts fp16x2 (t-major)
__device__ __nv_bfloat16 g_hbuf[2][B_*DH_];          // bf16 h exchange (recurrence)
__device__ float g_H[(size_t)B_*T_*DH_];             // H fp32 (for rsum)
__device__ uint32_t g_H16[(size_t)B_*T_*DH_/2];      // H fp16x2 (for attention GEMM)
__device__ float g_scores[B_*T_];
__device__ float g_rh[B_*1536];                      // [r | h_last] concat (fp32)
__device__ float g_hstar[B_*DH_];
__device__ int   g_perm[B_];
__device__ int   g_lens_s[B_];
__device__ unsigned g_barcnt;

__device__ __forceinline__ float sigf(float x) { return 1.0f / (1.0f + expf(-x)); }

__device__ __forceinline__ uint32_t f2tf32(float f) {
    uint32_t u;
    asm("cvt.rna.tf32.f32 %0, %1;" : "=r"(u) : "f"(f));
    return u;
}
__device__ __forceinline__ uint32_t pack_bf16(float lo, float hi) {
    uint32_t r;
    asm("cvt.rn.bf16x2.f32 %0, %1, %2;" : "=r"(r) : "f"(hi), "f"(lo));
    return r;
}
__device__ __forceinline__ uint32_t pack_h2(float lo, float hi) {
    uint32_t r;
    asm("cvt.rn.f16x2.f32 %0, %1, %2;" : "=r"(r) : "f"(hi), "f"(lo));
    return r;
}

__device__ __forceinline__ void mma_tf32(float* c,
                                         uint32_t a0, uint32_t a1, uint32_t a2, uint32_t a3,
                                         uint32_t b0, uint32_t b1) {
    asm volatile(
        "mma.sync.aligned.m16n8k8.row.col.f32.tf32.tf32.f32 "
        "{%0,%1,%2,%3},{%4,%5,%6,%7},{%8,%9},{%0,%1,%2,%3};"
        : "+f"(c[0]), "+f"(c[1]), "+f"(c[2]), "+f"(c[3])
        : "r"(a0), "r"(a1), "r"(a2), "r"(a3), "r"(b0), "r"(b1));
}
__device__ __forceinline__ void mma_f16(float* c,
                                        uint32_t a0, uint32_t a1, uint32_t a2, uint32_t a3,
                                        uint32_t b0, uint32_t b1) {
    asm volatile(
        "mma.sync.aligned.m16n8k16.row.col.f32.f16.f16.f32 "
        "{%0,%1,%2,%3},{%4,%5,%6,%7},{%8,%9},{%0,%1,%2,%3};"
        : "+f"(c[0]), "+f"(c[1]), "+f"(c[2]), "+f"(c[3])
        : "r"(a0), "r"(a1), "r"(a2), "r"(a3), "r"(b0), "r"(b1));
}
__device__ __forceinline__ void mma_bf16(float* c,
                                         uint32_t a0, uint32_t a1, uint32_t a2, uint32_t a3,
                                         uint32_t b0, uint32_t b1) {
    asm volatile(
        "mma.sync.aligned.m16n8k16.row.col.f32.bf16.bf16.f32 "
        "{%0,%1,%2,%3},{%4,%5,%6,%7},{%8,%9},{%0,%1,%2,%3};"
        : "+f"(c[0]), "+f"(c[1]), "+f"(c[2]), "+f"(c[3])
        : "r"(a0), "r"(a1), "r"(a2), "r"(a3), "r"(b0), "r"(b1));
}
__device__ __forceinline__ void ldsm4(uint32_t& r0, uint32_t& r1,
                                      uint32_t& r2, uint32_t& r3, uint32_t addr) {
    asm volatile("ldmatrix.sync.aligned.m8n8.x4.shared.b16 {%0,%1,%2,%3}, [%4];"
                 : "=r"(r0), "=r"(r1), "=r"(r2), "=r"(r3) : "r"(addr));
}

__device__ __forceinline__ void cpa16(uint32_t dst, const void* src) {
    asm volatile("cp.async.ca.shared.global [%0], [%1], 16;"
                 :: "r"(dst), "l"(src));
}
__device__ __forceinline__ void cpa_commit() {
    asm volatile("cp.async.commit_group;" ::: "memory");
}
template<int N>
__device__ __forceinline__ void cpa_wait() {
    asm volatile("cp.async.wait_group %0;" :: "n"(N) : "memory");
}

// ---------------- sort batch by length (descending), one block ---------------
__global__ void sort_kernel(const int* __restrict__ lens) {
    __shared__ int key[B_];
    int tid = threadIdx.x;
    key[tid] = ((128 - lens[tid]) << 8) | tid;
    __syncthreads();
    for (int k = 2; k <= B_; k <<= 1) {
        for (int j = k >> 1; j > 0; j >>= 1) {
            int ixj = tid ^ j;
            if (ixj > tid) {
                int a = key[tid], b = key[ixj];
                bool up = ((tid & k) == 0);
                if (up ? (a > b) : (a < b)) { key[tid] = b; key[ixj] = a; }
            }
            __syncthreads();
        }
    }
    g_perm[tid] = key[tid] & 255;
    g_lens_s[tid] = 128 - (key[tid] >> 8);
}

// ---------------- gather+convert x -> fp16 (t-major); gather tx fp32 ---------
__global__ void gatherx_kernel(const int* __restrict__ sent,
                               const int* __restrict__ target,
                               const float* __restrict__ emb,
                               const float* __restrict__ temb) {
    int row = blockIdx.x;
    int tid = threadIdx.x;  // 192
    if (row < B_ * T_) {
        int bs = row & 255, t = row >> 8;
        int token = sent[g_perm[bs] * T_ + t];
        const float2* src = (const float2*)(emb + (size_t)token * DW_);
        uint32_t* dst = g_x16 + (size_t)row * (DW_ / 2);
        float2 v0 = src[tid];
        float2 v1 = src[tid + 192];
        dst[tid] = pack_h2(v0.x, v0.y);
        dst[tid + 192] = pack_h2(v1.x, v1.y);
    } else {
        int bs = row - B_ * T_;
        const float4* src = (const float4*)(temb + (size_t)target[g_perm[bs]] * DW_);
        ((float4*)(g_tx + (size_t)bs * DW_))[tid] = src[tid];
    }
}

// ---------------- pack weights: W_ih top + Wh fp16 pairs, stack [Wp;Wx] ------
__global__ void convw_kernel(const float* __restrict__ W_ih,
                             const float* __restrict__ Wh,
                             const float* __restrict__ Wp,
                             const float* __restrict__ Wx) {
    int i = blockIdx.x * 256 + threadIdx.x;
    if (i < 384 * G_) {
        int k2 = i / G_, n = i - k2 * G_;
        g_wih16[i] = pack_h2(W_ih[(size_t)(2 * k2) * G_ + n],
                             W_ih[(size_t)(2 * k2 + 1) * G_ + n]);
    } else if (i < 384 * G_ + 384 * DH_) {
        int j = i - 384 * G_;
        int k2 = j / DH_, n = j - k2 * DH_;
        g_wh16[j] = pack_h2(Wh[(size_t)(2 * k2) * DH_ + n],
                            Wh[(size_t)(2 * k2 + 1) * DH_ + n]);
    } else {
        int j = i - 384 * G_ - 384 * DH_;
        if (j < 1536 * DH_)
            g_wpx[j] = (j < 768 * DH_) ? Wp[j] : Wx[j - 768 * DH_];
    }
}

// zero bf16 h (buffer 0), scores, barrier counter
__global__ void zeroall_kernel() {
    int i = blockIdx.x * 256 + threadIdx.x;
    if (i < B_ * DH_ / 2) ((uint32_t*)g_hbuf)[i] = 0u;
    if (i < B_ * T_) g_scores[i] = 0.0f;
    if (i == 0) g_barcnt = 0u;
}

// ---------------- fp16 cp.async pipelined 128x128 GEMM (ldmatrix A) ----------
// MODE 2: gin: C16 = fp16(acc + aux[(row&255)*auxStride + col])
// MODE 4: attn: atomicAdd(sc[(row&255)*T + (row>>8)], sum_col tanh(acc)*wv[col])
template<int MODE>
__global__ void __launch_bounds__(256, 2)
mm2h(const uint32_t* __restrict__ Au, const uint32_t* __restrict__ Bp,
     uint32_t* __restrict__ C16, int N,
     const float* __restrict__ aux, long long auxStride,
     const float* __restrict__ wv, float* __restrict__ sc,
     const int* __restrict__ exl) {
    constexpr int BM = 128, BN = 128, S = 3;
    constexpr int SA = 20;
    constexpr int SB = 136;
    constexpr int ASTG = BM * SA;
    constexpr int BSTG = 16 * SB;
    constexpr int KT = 768 / 32;      // 24

    const int m0 = blockIdx.y * BM;
    {
        int t = m0 >> 8;
        int half = (m0 >> 7) & 1;
        if (t >= exl[half * 128]) return;
    }

    extern __shared__ uint32_t smu[];
    uint32_t* As = smu;
    uint32_t* Bs = smu + S * ASTG;

    const int tid = threadIdx.x;
    const int lane = tid & 31;
    const int wid = tid >> 5;
    const int wm = wid & 1;
    const int wn = wid >> 1;
    const int n0 = blockIdx.x * BN;

    const int arow = tid >> 1;
    const int abase = (tid & 1) * 8;
    const uint32_t* aptr = Au + (size_t)(m0 + arow) * 384 + abase;
    const int brow = tid >> 4;
    const int bbase = (tid & 15) * 8;
    const uint32_t* bptr = Bp + (size_t)brow * N + n0 + bbase;

    const uint32_t As_sh = (uint32_t)__cvta_generic_to_shared(As);
    uint32_t rowoffA[4];
#pragma unroll
    for (int mt = 0; mt < 4; mt++)
        rowoffA[mt] = ((wm * 64 + mt * 16 + (lane & 15)) * SA + (lane >> 4) * 4) * 4;

    float acc[4][4][4];
#pragma unroll
    for (int i = 0; i < 4; i++)
#pragma unroll
        for (int j = 0; j < 4; j++)
#pragma unroll
            for (int q = 0; q < 4; q++) acc[i][j][q] = 0.0f;

    auto issue = [&](int kt) {
        int st = kt % S;
        uint32_t* as = As + st * ASTG;
        uint32_t* bs = Bs + st * BSTG;
        const uint32_t* ap = aptr + kt * 16;
        const uint32_t* bp = bptr + (size_t)kt * 16 * N;
        cpa16((uint32_t)__cvta_generic_to_shared(as + arow * SA + abase), ap);
        cpa16((uint32_t)__cvta_generic_to_shared(as + arow * SA + abase + 4), ap + 4);
        cpa16((uint32_t)__cvta_generic_to_shared(bs + brow * SB + bbase), bp);
        cpa16((uint32_t)__cvta_generic_to_shared(bs + brow * SB + bbase + 4), bp + 4);
    };

#pragma unroll
    for (int s = 0; s < S - 1; s++) { issue(s); cpa_commit(); }

    for (int kt = 0; kt < KT; kt++) {
        cpa_wait<S - 2>();
        __syncthreads();
        if (kt + S - 1 < KT) issue(kt + S - 1);
        cpa_commit();

        const int st = kt % S;
        const uint32_t abyte = As_sh + (st * ASTG) * 4;
        const uint32_t* bsU = Bs + st * BSTG;
#pragma unroll
        for (int ks = 0; ks < 2; ks++) {
            int kq = ks * 8 + (lane & 3);
            uint32_t af[4][4], bf[4][2];
#pragma unroll
            for (int mt = 0; mt < 4; mt++)
                ldsm4(af[mt][0], af[mt][1], af[mt][2], af[mt][3],
                      abyte + rowoffA[mt] + ks * 32);
#pragma unroll
            for (int nt = 0; nt < 4; nt++) {
                int n = wn * 32 + nt * 8 + (lane >> 2);
                bf[nt][0] = bsU[kq * SB + n];
                bf[nt][1] = bsU[(kq + 4) * SB + n];
            }
#pragma unroll
            for (int mt = 0; mt < 4; mt++)
#pragma unroll
                for (int nt = 0; nt < 4; nt++)
                    mma_f16(acc[mt][nt],
                            af[mt][0], af[mt][1], af[mt][2], af[mt][3],
                            bf[nt][0], bf[nt][1]);
        }
    }

    if (MODE == 4) {
#pragma unroll
        for (int mt = 0; mt < 4; mt++) {
            float pl = 0.0f, ph = 0.0f;
#pragma unroll
            for (int nt = 0; nt < 4; nt++) {
                int col = n0 + wn * 32 + nt * 8 + ((lane & 3) << 1);
                float w0 = wv[col], w1 = wv[col + 1];
                pl += tanhf(acc[mt][nt][0]) * w0 + tanhf(acc[mt][nt][1]) * w1;
                ph += tanhf(acc[mt][nt][2]) * w0 + tanhf(acc[mt][nt][3]) * w1;
            }
            pl += __shfl_xor_sync(0xffffffffu, pl, 1);
            pl += __shfl_xor_sync(0xffffffffu, pl, 2);
            ph += __shfl_xor_sync(0xffffffffu, ph, 1);
            ph += __shfl_xor_sync(0xffffffffu, ph, 2);
            if ((lane & 3) == 0) {
                int r = m0 + wm * 64 + mt * 16 + (lane >> 2);
                atomicAdd(&sc[(r & 255) * T_ + (r >> 8)], pl);
                atomicAdd(&sc[((r + 8) & 255) * T_ + ((r + 8) >> 8)], ph);
            }
        }
    } else {
        const int N2 = N >> 1;
#pragma unroll
        for (int mt = 0; mt < 4; mt++) {
#pragma unroll
            for (int nt = 0; nt < 4; nt++) {
                int r = m0 + wm * 64 + mt * 16 + (lane >> 2);
                int c = n0 + wn * 32 + nt * 8 + ((lane & 3) << 1);
                float v0 = acc[mt][nt][0], v1 = acc[mt][nt][1];
                float v2 = acc[mt][nt][2], v3 = acc[mt][nt][3];
                const float* ar  = aux + (size_t)(r & 255) * auxStride;
                const float* ar8 = aux + (size_t)((r + 8) & 255) * auxStride;
                v0 += ar[c];  v1 += ar[c + 1];
                v2 += ar8[c]; v3 += ar8[c + 1];
                C16[(size_t)r * N2 + (c >> 1)] = pack_h2(v0, v1);
                C16[(size_t)(r + 8) * N2 + (c >> 1)] = pack_h2(v2, v3);
            }
        }
    }
}

// ---------------- small tf32 GEMM (64x64 tiles) -------------------------------
// MODE 1: C = acc + aux[col];  MODE 6: C = tanh(acc)
template<int BM, int BN, int WM, int WN, int MODE>
__global__ void __launch_bounds__((BM/WM)*(BN/WN)*32)
mm_k(const float* __restrict__ A, const float* __restrict__ Bm,
     float* __restrict__ C, int M, int N, int K,
     const float* __restrict__ aux) {
    constexpr int BK = 16;
    constexpr int NWARP = (BM / WM) * (BN / WN);
    constexpr int NT = NWARP * 32;
    constexpr int SA = BK + 4;
    constexpr int SB = BN + 8;
    constexpr int MT = WM / 16;
    constexpr int NL = WN / 8;
    constexpr int AQ = (BM * 4) / NT;
    constexpr int BQ = (BN * 4) / NT;

    __shared__ __align__(16) uint32_t As[BM][SA];
    __shared__ __align__(16) uint32_t Bs[BK][SB];

    const int tid = threadIdx.x;
    const int lane = tid & 31;
    const int wid = tid >> 5;
    const int wm = wid % (BM / WM);
    const int wn = wid / (BM / WM);
    const int m0 = blockIdx.y * BM;
    const int n0 = blockIdx.x * BN;

    float acc[MT][NL][4];
#pragma unroll
    for (int i = 0; i < MT; i++)
#pragma unroll
        for (int j = 0; j < NL; j++)
#pragma unroll
            for (int q = 0; q < 4; q++) acc[i][j][q] = 0.0f;

    float4 pa[AQ], pb[BQ];
    const int KT = K / BK;

#pragma unroll
    for (int q = 0; q < AQ; q++) {
        int idx = tid + q * NT;
        pa[q] = *(const float4*)(A + (size_t)(m0 + (idx >> 2)) * K + ((idx & 3) << 2));
    }
#pragma unroll
    for (int q = 0; q < BQ; q++) {
        int idx = tid + q * NT;
        pb[q] = *(const float4*)(Bm + (size_t)(idx / (BN / 4)) * N + n0 + ((idx % (BN / 4)) << 2));
    }

    for (int kt = 0; kt < KT; kt++) {
#pragma unroll
        for (int q = 0; q < AQ; q++) {
            int idx = tid + q * NT;
            uint4 v = make_uint4(f2tf32(pa[q].x), f2tf32(pa[q].y),
                                 f2tf32(pa[q].z), f2tf32(pa[q].w));
            *(uint4*)&As[idx >> 2][(idx & 3) << 2] = v;
        }
#pragma unroll
        for (int q = 0; q < BQ; q++) {
            int idx = tid + q * NT;
            uint4 v = make_uint4(f2tf32(pb[q].x), f2tf32(pb[q].y),
                                 f2tf32(pb[q].z), f2tf32(pb[q].w));
            *(uint4*)&Bs[idx / (BN / 4)][(idx % (BN / 4)) << 2] = v;
        }
        __syncthreads();

        if (kt + 1 < KT) {
            int k0 = (kt + 1) * BK;
#pragma unroll
            for (int q = 0; q < AQ; q++) {
                int idx = tid + q * NT;
                pa[q] = *(const float4*)(A + (size_t)(m0 + (idx >> 2)) * K + k0 + ((idx & 3) << 2));
            }
#pragma unroll
            for (int q = 0; q < BQ; q++) {
                int idx = tid + q * NT;
                pb[q] = *(const float4*)(Bm + (size_t)(k0 + idx / (BN / 4)) * N + n0 + ((idx % (BN / 4)) << 2));
            }
        }

#pragma unroll
        for (int ks = 0; ks < 2; ks++) {
            uint32_t af[MT][4];
            uint32_t bf[NL][2];
            int kc = ks * 8 + (lane & 3);
#pragma unroll
            for (int mt = 0; mt < MT; mt++) {
                int r = wm * WM + mt * 16 + (lane >> 2);
                af[mt][0] = As[r][kc];
                af[mt][1] = As[r + 8][kc];
                af[mt][2] = As[r][kc + 4];
                af[mt][3] = As[r + 8][kc + 4];
            }
#pragma unroll
            for (int nt = 0; nt < NL; nt++) {
                int n = wn * WN + nt * 8 + (lane >> 2);
                bf[nt][0] = Bs[kc][n];
                bf[nt][1] = Bs[kc + 4][n];
            }
#pragma unroll
            for (int mt = 0; mt < MT; mt++)
#pragma unroll
                for (int nt = 0; nt < NL; nt++)
                    mma_tf32(acc[mt][nt],
                             af[mt][0], af[mt][1], af[mt][2], af[mt][3],
                             bf[nt][0], bf[nt][1]);
        }
        __syncthreads();
    }

#pragma unroll
    for (int mt = 0; mt < MT; mt++) {
#pragma unroll
        for (int nt = 0; nt < NL; nt++) {
            int r = m0 + wm * WM + mt * 16 + (lane >> 2);
            int c = n0 + wn * WN + nt * 8 + ((lane & 3) << 1);
            float v0 = acc[mt][nt][0], v1 = acc[mt][nt][1];
            float v2 = acc[mt][nt][2], v3 = acc[mt][nt][3];
            if (MODE == 1) {
                v0 += aux[c]; v1 += aux[c + 1];
                v2 += aux[c]; v3 += aux[c + 1];
            }
            if (MODE == 6) {
                v0 = tanhf(v0); v1 = tanhf(v1);
                v2 = tanhf(v2); v3 = tanhf(v3);
            }
            *(float2*)&C[(size_t)r * N + c] = make_float2(v0, v1);
            *(float2*)&C[(size_t)(r + 8) * N + c] = make_float2(v2, v3);
        }
    }
}

// ---------------- persistent fused LSTM recurrence (bf16 MMA, cp.async) ------
// Identical structure to the R8/R10 proven version; h_last -> g_rh[:,768:].
__global__ void __launch_bounds__(256, 1)
lstm_persist(const float* __restrict__ W_hh) {
    extern __shared__ uint32_t sm_[];
    uint32_t* ws = sm_;                        // 12288
    uint32_t* Ab = sm_ + 12288;                // 34816
    int* slens = (int*)(sm_ + 12288 + 34816);
    int* nact  = (int*)(sm_ + 12288 + 34816 + 256);

    const int tid = threadIdx.x;
    const int lane = tid & 31;
    const int w = tid >> 5;
    const int nb = blockIdx.x;

    for (int i = tid; i < 12288; i += 256) {
        int nt = i / 3072;
        int rem = i - nt * 3072;
        int k2 = rem >> 3, nn = rem & 7;
        int col = nt * 768 + nb * 8 + nn;
        float w0 = W_hh[(size_t)(2 * k2) * G_ + col];
        float w1 = W_hh[(size_t)(2 * k2 + 1) * G_ + col];
        ws[i] = pack_bf16(w0, w1);
    }
    slens[tid] = g_lens_s[tid];
    __syncthreads();
    for (int i = tid; i < T_; i += 256) {
        int c = 0;
        for (int b = 0; b < B_; b++) c += (slens[b] > i) ? 1 : 0;
        int n32 = (c + 31) & ~31;
        nact[i] = n32 > 256 ? 256 : n32;
    }
    __syncthreads();

    const uint32_t Ab_sh = (uint32_t)__cvta_generic_to_shared(Ab);
    uint32_t rowoffA[2];
#pragma unroll
    for (int mt = 0; mt < 2; mt++)
        rowoffA[mt] = ((w * 32 + mt * 16 + (lane & 15)) * 68 + (lane >> 4) * 4) * 4;

    float c_reg[2][4], h_reg[2][4];
#pragma unroll
    for (int i = 0; i < 2; i++)
#pragma unroll
        for (int q = 0; q < 4; q++) { c_reg[i][q] = 0.0f; h_reg[i][q] = 0.0f; }

    unsigned epoch = 0;

    for (int t = 0; t < T_; t++) {
        const uint32_t* hcur = (const uint32_t*)g_hbuf[t & 1];
        __nv_bfloat16* hnxt = g_hbuf[(t + 1) & 1];
        const int n32 = nact[t];
        const bool sact = (tid < n32);
        const bool wact = (w * 32 < n32);

        float acc[2][4][4];
#pragma unroll
        for (int i = 0; i < 2; i++)
#pragma unroll
            for (int j = 0; j < 4; j++)
#pragma unroll
                for (int q = 0; q < 4; q++) acc[i][j][q] = 0.0f;

        const uint32_t* hrow = hcur + (size_t)tid * 384;
        const uint32_t dstrow = Ab_sh + tid * 68 * 4;

        if (sact) {
#pragma unroll
            for (int j = 0; j < 16; j++)
                cpa16(dstrow + j * 16, hrow + j * 4);
        }
        cpa_commit();

        for (int cch = 0; cch < 6; cch++) {
            cpa_wait<0>();
            __syncthreads();
            if (cch < 5) {
                if (sact) {
                    uint32_t d = dstrow + (((cch + 1) & 1) ? 17408u * 4u : 0u);
                    const uint32_t* s = hrow + (cch + 1) * 64;
#pragma unroll
                    for (int j = 0; j < 16; j++)
                        cpa16(d + j * 16, s + j * 4);
                }
                cpa_commit();
            }
            if (wact) {
                const uint32_t abyte = Ab_sh + (cch & 1) * 17408 * 4;
#pragma unroll
                for (int s = 0; s < 8; s++) {
                    int k2 = cch * 64 + s * 8 + (lane & 3);
                    uint32_t af[2][4], bf[4][2];
#pragma unroll
                    for (int mt = 0; mt < 2; mt++)
                        ldsm4(af[mt][0], af[mt][1], af[mt][2], af[mt][3],
                              abyte + rowoffA[mt] + s * 32);
#pragma unroll
                    for (int nt = 0; nt < 4; nt++) {
                        bf[nt][0] = ws[nt * 3072 + k2 * 8 + (lane >> 2)];
                        bf[nt][1] = ws[nt * 3072 + (k2 + 4) * 8 + (lane >> 2)];
                    }
#pragma unroll
                    for (int mt = 0; mt < 2; mt++)
#pragma unroll
                        for (int nt = 0; nt < 4; nt++)
                            mma_bf16(acc[mt][nt],
                                     af[mt][0], af[mt][1], af[mt][2], af[mt][3],
                                     bf[nt][0], bf[nt][1]);
                }
            }
        }

        int jcol = nb * 8 + ((lane & 3) << 1);
#pragma unroll
        for (int mt = 0; mt < 2; mt++) {
#pragma unroll
            for (int half = 0; half < 2; half++) {
                int r = w * 32 + mt * 16 + (lane >> 2) + half * 8;
                bool valid = (t < slens[r]);
                float2 bi = make_float2(0.f, 0.f), bff = bi, bg = bi, bo = bi;
                if (valid) {
                    const uint32_t* gp = g_gin16 + ((size_t)(t * B_ + r)) * (G_ / 2) + (jcol >> 1);
                    bi  = __half22float2(*(const __half2*)&gp[0]);
                    bff = __half22float2(*(const __half2*)&gp[384]);
                    bg  = __half22float2(*(const __half2*)&gp[768]);
                    bo  = __half22float2(*(const __half2*)&gp[1152]);
                }
                float hv0, hv1;
#pragma unroll
                for (int sub = 0; sub < 2; sub++) {
                    int q = half * 2 + sub;
                    float iv = acc[mt][0][q] + (sub ? bi.y : bi.x);
                    float fv = acc[mt][1][q] + (sub ? bff.y : bff.x);
                    float gv = acc[mt][2][q] + (sub ? bg.y : bg.x);
                    float ov = acc[mt][3][q] + (sub ? bo.y : bo.x);
                    float cn = sigf(fv) * c_reg[mt][q] + sigf(iv) * tanhf(gv);
                    float hn = sigf(ov) * tanhf(cn);
                    c_reg[mt][q] = valid ? cn : c_reg[mt][q];
                    float hv = valid ? hn : h_reg[mt][q];
                    h_reg[mt][q] = hv;
                    if (sub == 0) hv0 = hv; else hv1 = hv;
                }
                *(uint32_t*)&hnxt[(size_t)r * DH_ + jcol] = pack_bf16(hv0, hv1);
                *(float2*)&g_H[((size_t)(t * B_ + r)) * DH_ + jcol] = make_float2(hv0, hv1);
                g_H16[((size_t)(t * B_ + r)) * (DH_ / 2) + (jcol >> 1)] = pack_h2(hv0, hv1);
                if (t == T_ - 1)
                    *(float2*)&g_rh[(size_t)r * 1536 + 768 + jcol] = make_float2(hv0, hv1);
            }
        }

        // ---- grid barrier ----
        __syncthreads();
        if (tid == 0) {
            asm volatile("red.release.gpu.global.add.u32 [%0], %1;"
                         :: "l"(&g_barcnt), "r"(1u) : "memory");
            epoch++;
            unsigned target = epoch * NBLK;
            unsigned v;
            do {
                asm volatile("ld.acquire.gpu.global.u32 %0, [%1];"
                             : "=r"(v) : "l"(&g_barcnt));
                if (v < target) __nanosleep(64);
            } while (v < target);
        }
        __syncthreads();
    }
}

// ---------------- fused masked softmax + r = alpha.H -> g_rh[:, :768] --------
__global__ void softrsum_kernel() {
    int b = blockIdx.x;
    int tid = threadIdx.x;  // 256
    int lane = tid & 31, wid = tid >> 5;
    __shared__ float al[T_];
    __shared__ float red[8], red2[8];
    __shared__ int slen;
    if (tid == 0) slen = g_lens_s[b];
    __syncthreads();
    int len = slen;
    float s = (tid < len) ? g_scores[b * T_ + tid] : -1e30f;

    float m = s;
#pragma unroll
    for (int off = 16; off > 0; off >>= 1)
        m = fmaxf(m, __shfl_down_sync(0xffffffffu, m, off));
    if (lane == 0) red[wid] = m;
    __syncthreads();
    if (tid == 0) {
        float mm = red[0];
#pragma unroll
        for (int i = 1; i < 8; i++) mm = fmaxf(mm, red[i]);
        red[0] = mm;
    }
    __syncthreads();
    float mx = red[0];

    float e = (tid < len) ? expf(s - mx) : 0.0f;
    float sum = e;
#pragma unroll
    for (int off = 16; off > 0; off >>= 1)
        sum += __shfl_down_sync(0xffffffffu, sum, off);
    if (lane == 0) red2[wid] = sum;
    __syncthreads();
    if (tid == 0) {
        float tt = 0.0f;
#pragma unroll
        for (int i = 0; i < 8; i++) tt += red2[i];
        red2[0] = tt;
    }
    __syncthreads();
    float tot = red2[0];
    if (tid < T_) al[tid] = e / tot;
    __syncthreads();

    float a0 = 0.0f, a1 = 0.0f, a2 = 0.0f;
#pragma unroll 4
    for (int t = 0; t < len; t++) {
        float a = al[t];
        const float* Hr = g_H + ((size_t)(t * B_ + b)) * DH_;
        a0 += a * Hr[tid];
        a1 += a * Hr[tid + 256];
        a2 += a * Hr[tid + 512];
    }
    g_rh[b * 1536 + tid] = a0;
    g_rh[b * 1536 + tid + 256] = a1;
    g_rh[b * 1536 + tid + 512] = a2;
}

// ---------------- logit = h_star @ W_lin + b_lin (unsort at write) -----------
__global__ void logit_kernel(const float* __restrict__ Wl,
                             const float* __restrict__ bl,
                             float* __restrict__ out) {
    int b = blockIdx.x;
    int tid = threadIdx.x;
    float p0 = 0.0f, p1 = 0.0f, p2 = 0.0f;
    for (int j = tid; j < DH_; j += 128) {
        float v = g_hstar[b * DH_ + j];
        p0 += v * Wl[j * 3 + 0];
        p1 += v * Wl[j * 3 + 1];
        p2 += v * Wl[j * 3 + 2];
    }
#pragma unroll
    for (int off = 16; off > 0; off >>= 1) {
        p0 += __shfl_down_sync(0xffffffffu, p0, off);
        p1 += __shfl_down_sync(0xffffffffu, p1, off);
        p2 += __shfl_down_sync(0xffffffffu, p2, off);
    }
    __shared__ float sm[3][4];
    if ((tid & 31) == 0) {
        sm[0][tid >> 5] = p0; sm[1][tid >> 5] = p1; sm[2][tid >> 5] = p2;
    }
    __syncthreads();
    if (tid < 3) {
        float s = sm[tid][0] + sm[tid][1] + sm[tid][2] + sm[tid][3];
        out[g_perm[b] * 3 + tid] = s + bl[tid];
    }
}

// ---------------- launch ------------------------------------------------------
extern "C" void kernel_launch(void* const* d_in, const int* in_sizes, int n_in,
                              void* d_out, int out_size) {
    const int*   sent   = (const int*)d_in[0];
    const int*   target = (const int*)d_in[1];
    const int*   lens   = (const int*)d_in[2];
    const float* emb    = (const float*)d_in[3];
    const float* temb   = (const float*)d_in[4];
    const float* W_ih   = (const float*)d_in[5];   // (1536, 3072)
    const float* W_hh   = (const float*)d_in[6];   // (768, 3072)
    const float* b_lstm = (const float*)d_in[7];   // (3072,)
    const float* Wh     = (const float*)d_in[8];   // (768, 768)
    // d_in[9] = Wv — unused: aspect score term constant over t, cancels in softmax.
    const float* w_att  = (const float*)d_in[10];  // (1536,), first 768 used
    const float* Wp     = (const float*)d_in[11];
    const float* Wx     = (const float*)d_in[12];
    const float* W_lin  = (const float*)d_in[13];  // (768, 3)
    const float* b_lin  = (const float*)d_in[14];
    float* out = (float*)d_out;

    float *ptx, *ptxp, *prh, *pwpx, *phstar, *pscores;
    uint32_t *px16, *pwih16, *pwh16, *pgin16, *pH16;
    int *plens_s;
    cudaGetSymbolAddress((void**)&ptx,     g_tx);
    cudaGetSymbolAddress((void**)&ptxp,    g_txp);
    cudaGetSymbolAddress((void**)&prh,     g_rh);
    cudaGetSymbolAddress((void**)&pwpx,    g_wpx);
    cudaGetSymbolAddress((void**)&phstar,  g_hstar);
    cudaGetSymbolAddress((void**)&pscores, g_scores);
    cudaGetSymbolAddress((void**)&plens_s, g_lens_s);
    cudaGetSymbolAddress((void**)&px16,    g_x16);
    cudaGetSymbolAddress((void**)&pwih16,  g_wih16);
    cudaGetSymbolAddress((void**)&pwh16,   g_wh16);
    cudaGetSymbolAddress((void**)&pgin16,  g_gin16);
    cudaGetSymbolAddress((void**)&pH16,    g_H16);

    const int LSTM_SMEM = (12288 + 34816) * 4 + 256 * 4 + 128 * 4;  // 189,952 B
    cudaFuncSetAttribute(lstm_persist,
                         cudaFuncAttributeMaxDynamicSharedMemorySize, LSTM_SMEM);
    const int MM2H_SMEM = 3 * (2560 + 2176) * 4;  // 56,832 B (2 CTAs/SM)
    cudaFuncSetAttribute(mm2h<2>,
                         cudaFuncAttributeMaxDynamicSharedMemorySize, MM2H_SMEM);
    cudaFuncSetAttribute(mm2h<4>,
                         cudaFuncAttributeMaxDynamicSharedMemorySize, MM2H_SMEM);

    // 1. sort batch by length (descending)
    sort_kernel<<<1, B_>>>(lens);

    // 2. gather+convert x -> fp16 (t-major), gather tx (fp32)
    gatherx_kernel<<<B_ * T_ + B_, 192>>>(sent, target, emb, temb);

    // 3. pack W_ih_top / Wh fp16 pairs + stack [Wp;Wx]
    convw_kernel<<<(384 * G_ + 384 * DH_ + 1536 * DH_ + 255) / 256, 256>>>(
        W_ih, Wh, Wp, Wx);

    // 4. zero h buffer (bf16), scores, barrier counter
    zeroall_kernel<<<(B_ * DH_ / 2 + 255) / 256, 256>>>();

    // 5. txp = tx @ W_ih[768:,:] + b_lstm      (256 x 3072, K=768, tf32)
    mm_k<64, 64, 32, 32, 1><<<dim3(G_ / 64, B_ / 64), 128>>>(
        ptx, W_ih + (size_t)768 * G_, ptxp, B_, G_, DW_, b_lstm);

    // 6. gin = x16 @ Wih16 + txp[bs]   (fp16 MMA, ldmatrix, early-exit)
    mm2h<2><<<dim3(G_ / 128, (B_ * T_) / 128), 256, MM2H_SMEM>>>(
        px16, pwih16, pgin16, G_,
        ptxp, G_, nullptr, nullptr, plens_s);

    // 7. fused persistent LSTM recurrence
    lstm_persist<<<NBLK, 256, LSTM_SMEM>>>(W_hh);

    // 8. attention scores (fp16 MMA, ldmatrix, early-exit)
    mm2h<4><<<dim3(DH_ / 128, (B_ * T_) / 128), 256, MM2H_SMEM>>>(
        pH16, pwh16, nullptr, DH_,
        nullptr, 0, w_att, pscores, plens_s);

    // 9. fused masked softmax + r-sum -> g_rh[:, :768]
    softrsum_kernel<<<B_, 256>>>();

    // 10. h_star = tanh([r | h_last] @ [Wp; Wx])   (K=1536, tanh epilogue)
    mm_k<64, 64, 32, 32, 6><<<dim3(DH_ / 64, B_ / 64), 128>>>(
        prh, pwpx, phstar, B_, DH_, 1536, nullptr);

    // 11. logits (unsorted write)
    logit_kernel<<<B_, 128>>>(W_lin, b_lin, out);
}